// round 12
// baseline (speedup 1.0000x reference)
#include <cuda_runtime.h>

// Problem constants (fixed by dataset)
#define NN     40000      // nodes
#define NE     640000     // edges
#define DD     128        // feature dim
#define NBATCH 32         // graphs
#define IMGD   4096       // image feature dim
#define SCAN_BLOCKS 157           // ceil(NN/256)
#define IMG_KSPLIT  32            // k_img1 k-splits (1024 blocks total)
#define CROWS   16                // rows per conv block
#define CTHREADS 512
#define CONV_BLOCKS (NN / CROWS)  // 2500
#define ECAP    1024              // smem edge records per conv block

// ---------------- scratch (static device globals; zero at module load) --------
// Self-restoring invariant: g_hist, g_q, g_sums are zero before every replay;
// each consumer re-zeroes what it read. Everything else is overwritten first.
__device__ int   g_hist[NN];
__device__ float g_dis[NN];
__device__ int   g_off[NN + 1];
__device__ int   g_cur[NN];
__device__ int   g_bsum[SCAN_BLOCKS];
__device__ int2  g_e[NE];         // (src, __float_as_int(w)) dst-sorted
__device__ float g_Y[NN * DD];    // feature ping buffer (dis-scaled)
__device__ float g_T[NN * DD];    // feature pong buffer
__device__ float g_q[NBATCH * IMGD];
__device__ float g_sums[NBATCH * DD];

__device__ __forceinline__ void red_add(float* p, float v) {
    asm volatile("red.global.add.f32 [%0], %1;" :: "l"(p), "f"(v) : "memory");
}

// ---------------- edge histogram (int only) ------------------------------------
__global__ void k_hist(const int* __restrict__ dst) {
    int e = blockIdx.x * blockDim.x + threadIdx.x;
    if (e < NE) atomicAdd(&g_hist[dst[e]], 1);
}

// ---------------- scan part 1: per-block exclusive scan (+hist reset) ----------
__global__ void k_scan1() {
    __shared__ int s[256];
    int tid = threadIdx.x;
    int i = blockIdx.x * 256 + tid;
    int v = 0;
    if (i < NN) { v = g_hist[i]; g_hist[i] = 0; }   // read + reset (self-restoring)
    s[tid] = v; __syncthreads();
    for (int o = 1; o < 256; o <<= 1) {
        int t = (tid >= o) ? s[tid - o] : 0;
        __syncthreads();
        s[tid] += t;
        __syncthreads();
    }
    if (i < NN) g_off[i] = s[tid] - v;
    if (tid == 255) g_bsum[blockIdx.x] = s[255];
}

// ---------------- scan part 2+3 fused: each block rescans block sums -----------
__global__ void k_scan23() {
    __shared__ int s[256];
    int tid = threadIdx.x;
    int v = (tid < SCAN_BLOCKS) ? g_bsum[tid] : 0;
    s[tid] = v; __syncthreads();
    for (int o = 1; o < 256; o <<= 1) {
        int t = (tid >= o) ? s[tid - o] : 0;
        __syncthreads();
        s[tid] += t;
        __syncthreads();
    }
    int base = (blockIdx.x > 0) ? s[blockIdx.x - 1] : 0;   // inclusive -> excl base
    int i = blockIdx.x * 256 + tid;
    if (i < NN) {
        int val = g_off[i] + base;
        g_off[i] = val;
        g_cur[i] = val;
    }
    if (i == 0) g_off[NN] = NE;
}

// ---------------- image GEMM 1: g_q += images @ W_img (deep split-K) -----------
// grid: 32 col-tiles x 32 K-splits = 1024 blocks; images tile staged in smem.
__global__ void __launch_bounds__(256) k_img1(const float* __restrict__ images,
                                              const float* __restrict__ Wimg) {
    __shared__ float4 simg[32 * 32];   // [row][k4] for this block's 128-k chunk
    int ct = blockIdx.x & 31;
    int ks = blockIdx.x >> 5;
    int tid = threadIdx.x;
    int kbase = ks * 128;
    const float4* img4 = (const float4*)images;
    for (int i = tid; i < 1024; i += 256) {
        int r = i >> 5, k4 = i & 31;
        simg[i] = img4[r * (IMGD / 4) + (kbase >> 2) + k4];
    }
    __syncthreads();
    int c = tid & 31;
    int rg = tid >> 5;               // 8 row groups x 4 rows = 32 rows
    const float4* W4 = (const float4*)Wimg + (size_t)kbase * (IMGD / 4) + ct * 32 + c;
    float acc[4][4] = {};
#pragma unroll 2
    for (int k4 = 0; k4 < 32; k4++) {
        const float4* Wp = W4 + (size_t)k4 * 4 * (IMGD / 4);
        float4 w0 = __ldg(Wp);
        float4 w1 = __ldg(Wp + (IMGD / 4));
        float4 w2 = __ldg(Wp + 2 * (IMGD / 4));
        float4 w3 = __ldg(Wp + 3 * (IMGD / 4));
        float4 a0 = simg[(rg * 4 + 0) * 32 + k4];
        float4 a1 = simg[(rg * 4 + 1) * 32 + k4];
        float4 a2 = simg[(rg * 4 + 2) * 32 + k4];
        float4 a3 = simg[(rg * 4 + 3) * 32 + k4];
#define IMG_FMA(rr, av) \
        acc[rr][0] = fmaf(av.x, w0.x, acc[rr][0]); acc[rr][1] = fmaf(av.x, w0.y, acc[rr][1]); \
        acc[rr][2] = fmaf(av.x, w0.z, acc[rr][2]); acc[rr][3] = fmaf(av.x, w0.w, acc[rr][3]); \
        acc[rr][0] = fmaf(av.y, w1.x, acc[rr][0]); acc[rr][1] = fmaf(av.y, w1.y, acc[rr][1]); \
        acc[rr][2] = fmaf(av.y, w1.z, acc[rr][2]); acc[rr][3] = fmaf(av.y, w1.w, acc[rr][3]); \
        acc[rr][0] = fmaf(av.z, w2.x, acc[rr][0]); acc[rr][1] = fmaf(av.z, w2.y, acc[rr][1]); \
        acc[rr][2] = fmaf(av.z, w2.z, acc[rr][2]); acc[rr][3] = fmaf(av.z, w2.w, acc[rr][3]); \
        acc[rr][0] = fmaf(av.w, w3.x, acc[rr][0]); acc[rr][1] = fmaf(av.w, w3.y, acc[rr][1]); \
        acc[rr][2] = fmaf(av.w, w3.z, acc[rr][2]); acc[rr][3] = fmaf(av.w, w3.w, acc[rr][3]);
        IMG_FMA(0, a0)
        IMG_FMA(1, a1)
        IMG_FMA(2, a2)
        IMG_FMA(3, a3)
#undef IMG_FMA
    }
    int c0 = ct * 128 + c * 4;
#pragma unroll
    for (int rr = 0; rr < 4; rr++) {
        float* p = &g_q[(rg * 4 + rr) * IMGD + c0];
        red_add(p + 0, acc[rr][0]); red_add(p + 1, acc[rr][1]);
        red_add(p + 2, acc[rr][2]); red_add(p + 3, acc[rr][3]);
    }
}

// ---------------- scatter edges into dst-sorted int2 records -------------------
__global__ void k_scatter(const int* __restrict__ src, const int* __restrict__ dst,
                          const float* __restrict__ ew) {
    int e = blockIdx.x * blockDim.x + threadIdx.x;
    if (e < NE) {
        int d = dst[e];
        int p = atomicAdd(&g_cur[d], 1);
        g_e[p] = make_int2(src[e], __float_as_int(ew[e]));
    }
}

// ---------------- embedding gather + deg (segment sum of sorted w) + dis -------
__global__ void k_gather(const int* __restrict__ ids, const float* __restrict__ emb) {
    int t = blockIdx.x * blockDim.x + threadIdx.x;
    int row = t >> 5, lane = t & 31;
    if (row >= NN) return;
    int j0 = g_off[row], j1 = g_off[row + 1];
    float w = 0.0f;
    for (int j = j0 + lane; j < j1; j += 32) w += __int_as_float(g_e[j].y);
#pragma unroll
    for (int o = 16; o > 0; o >>= 1) w += __shfl_xor_sync(0xffffffffu, w, o);
    float ds = rsqrtf(1.0f + w);    // self-loop weight 1 included
    if (lane == 0) g_dis[row] = ds;
    int id = ids[row];
    float4 v = ((const float4*)emb)[id * (DD / 4) + lane];
    v.x *= ds; v.y *= ds; v.z *= ds; v.w *= ds;
    ((float4*)g_Y)[row * (DD / 4) + lane] = v;
}

// ---------------- fused GCN conv ------------------------------------------------
// 512 threads, 16 rows/block, WARP PER ROW aggregation with smem edge preload.
// MODE 0: src g_Y -> dst g_T, relu epilogue      (conv 1)
// MODE 1: src g_T -> dst g_Y, relu epilogue      (conv 2)
// MODE 2: src g_Y -> mean-pool into g_sums       (conv 3)
template <int MODE>
__global__ void __launch_bounds__(CTHREADS, 2) k_conv(const float* __restrict__ W,
                                                      const float* __restrict__ bias,
                                                      const int* __restrict__ batch) {
    __shared__ float As[CROWS * DD];   // 8 KB: aggregated (dis-scaled) rows
    __shared__ int2  se[ECAP];         // 8 KB: this block's edge records
    int tid = threadIdx.x;
    int wid = tid >> 5, lane = tid & 31;
    int r0 = blockIdx.x * CROWS;
    const float4* Y4 = (const float4*)((MODE == 1) ? g_T : g_Y);

    // Phase 0: coalesced preload of the block's edge segment into smem
    int e0 = g_off[r0];
    int nseg = g_off[r0 + CROWS] - e0;
    int nload = (nseg < ECAP) ? nseg : ECAP;
    for (int i = tid; i < nload; i += CTHREADS) se[i] = g_e[e0 + i];
    __syncthreads();
    const int2* ep = (nseg <= ECAP) ? (const int2*)se : (const int2*)(g_e + e0);

    // Phase 1: warp per row; addresses come from smem -> deep-MLP gathers
    {
        int row = r0 + wid;
        float ds = g_dis[row];
        float4 acc0 = Y4[row * 32 + lane];     // self loop
        float4 acc1 = make_float4(0.f, 0.f, 0.f, 0.f);
        int j = g_off[row] - e0, je = g_off[row + 1] - e0;
        for (; j + 8 <= je; j += 8) {
            int2 c0 = ep[j + 0], c1 = ep[j + 1], c2 = ep[j + 2], c3 = ep[j + 3];
            int2 c4 = ep[j + 4], c5 = ep[j + 5], c6 = ep[j + 6], c7 = ep[j + 7];
            float4 v0 = Y4[c0.x * 32 + lane];
            float4 v1 = Y4[c1.x * 32 + lane];
            float4 v2 = Y4[c2.x * 32 + lane];
            float4 v3 = Y4[c3.x * 32 + lane];
            float4 v4 = Y4[c4.x * 32 + lane];
            float4 v5 = Y4[c5.x * 32 + lane];
            float4 v6 = Y4[c6.x * 32 + lane];
            float4 v7 = Y4[c7.x * 32 + lane];
            float w0 = __int_as_float(c0.y), w1 = __int_as_float(c1.y);
            float w2 = __int_as_float(c2.y), w3 = __int_as_float(c3.y);
            float w4 = __int_as_float(c4.y), w5 = __int_as_float(c5.y);
            float w6 = __int_as_float(c6.y), w7 = __int_as_float(c7.y);
            acc0.x = fmaf(w0, v0.x, acc0.x); acc0.y = fmaf(w0, v0.y, acc0.y);
            acc0.z = fmaf(w0, v0.z, acc0.z); acc0.w = fmaf(w0, v0.w, acc0.w);
            acc1.x = fmaf(w1, v1.x, acc1.x); acc1.y = fmaf(w1, v1.y, acc1.y);
            acc1.z = fmaf(w1, v1.z, acc1.z); acc1.w = fmaf(w1, v1.w, acc1.w);
            acc0.x = fmaf(w2, v2.x, acc0.x); acc0.y = fmaf(w2, v2.y, acc0.y);
            acc0.z = fmaf(w2, v2.z, acc0.z); acc0.w = fmaf(w2, v2.w, acc0.w);
            acc1.x = fmaf(w3, v3.x, acc1.x); acc1.y = fmaf(w3, v3.y, acc1.y);
            acc1.z = fmaf(w3, v3.z, acc1.z); acc1.w = fmaf(w3, v3.w, acc1.w);
            acc0.x = fmaf(w4, v4.x, acc0.x); acc0.y = fmaf(w4, v4.y, acc0.y);
            acc0.z = fmaf(w4, v4.z, acc0.z); acc0.w = fmaf(w4, v4.w, acc0.w);
            acc1.x = fmaf(w5, v5.x, acc1.x); acc1.y = fmaf(w5, v5.y, acc1.y);
            acc1.z = fmaf(w5, v5.z, acc1.z); acc1.w = fmaf(w5, v5.w, acc1.w);
            acc0.x = fmaf(w6, v6.x, acc0.x); acc0.y = fmaf(w6, v6.y, acc0.y);
            acc0.z = fmaf(w6, v6.z, acc0.z); acc0.w = fmaf(w6, v6.w, acc0.w);
            acc1.x = fmaf(w7, v7.x, acc1.x); acc1.y = fmaf(w7, v7.y, acc1.y);
            acc1.z = fmaf(w7, v7.z, acc1.z); acc1.w = fmaf(w7, v7.w, acc1.w);
        }
        for (; j < je; j++) {
            int2 e = ep[j];
            float w = __int_as_float(e.y);
            float4 v = Y4[e.x * 32 + lane];
            acc0.x = fmaf(w, v.x, acc0.x); acc0.y = fmaf(w, v.y, acc0.y);
            acc0.z = fmaf(w, v.z, acc0.z); acc0.w = fmaf(w, v.w, acc0.w);
        }
        float4 r;
        r.x = (acc0.x + acc1.x) * ds; r.y = (acc0.y + acc1.y) * ds;
        r.z = (acc0.z + acc1.z) * ds; r.w = (acc0.w + acc1.w) * ds;
        ((float4*)As)[wid * 32 + lane] = r;     // conflict-free
    }
    __syncthreads();

    // Phase 2: 16x128 @ 128x128 GEMM; a via smem broadcast, W via L1
    int c = tid & 31, rg = tid >> 5;     // rg = output row (0..15)
    const float4* W4 = (const float4*)W;
    float acc[4] = {0.f, 0.f, 0.f, 0.f};
#pragma unroll 8
    for (int k = 0; k < DD; k++) {
        float a = As[rg * DD + k];               // broadcast
        float4 w = __ldg(&W4[k * 32 + c]);       // L1-resident after warm
        acc[0] = fmaf(a, w.x, acc[0]); acc[1] = fmaf(a, w.y, acc[1]);
        acc[2] = fmaf(a, w.z, acc[2]); acc[3] = fmaf(a, w.w, acc[3]);
    }
    float4 b4 = ((const float4*)bias)[c];
    if (MODE != 2) {
        float* Out = (MODE == 0) ? g_T : g_Y;
        int row = r0 + rg;
        float dso = g_dis[row];
        float4 o = make_float4(fmaxf(acc[0] + b4.x, 0.f) * dso,
                               fmaxf(acc[1] + b4.y, 0.f) * dso,
                               fmaxf(acc[2] + b4.z, 0.f) * dso,
                               fmaxf(acc[3] + b4.w, 0.f) * dso);
        ((float4*)Out)[row * 32 + c] = o;
    } else {
        float4 o = make_float4(acc[0] + b4.x, acc[1] + b4.y,
                               acc[2] + b4.z, acc[3] + b4.w);
        int b0 = batch[r0], bL = batch[r0 + CROWS - 1];
        if (b0 == bL) {
            // whole block in one graph: smem pre-reduce, 128 atomics/block
            __syncthreads();                   // done reading As; reuse as staging
            float4* sp = (float4*)As;
            sp[rg * 32 + c] = o;
            __syncthreads();
            if (tid < 32) {
                float4 a = sp[tid];
#pragma unroll
                for (int g = 1; g < CROWS; g++) {
                    float4 t = sp[g * 32 + tid];
                    a.x += t.x; a.y += t.y; a.z += t.z; a.w += t.w;
                }
                float* pp = &g_sums[b0 * DD + tid * 4];
                red_add(pp + 0, a.x); red_add(pp + 1, a.y);
                red_add(pp + 2, a.z); red_add(pp + 3, a.w);
            }
        } else {
            int bb = batch[r0 + rg];
            float* pp = &g_sums[bb * DD + c * 4];
            red_add(pp + 0, o.x); red_add(pp + 1, o.y);
            red_add(pp + 2, o.z); red_add(pp + 3, o.w);
        }
    }
}

// ---------------- image head: out = l2norm((q + b_img) @ W_i + b_i) ------------
// Resets g_q row to zero afterwards (self-restoring for next replay).
__global__ void __launch_bounds__(128) k_img2(const float* __restrict__ Wi,
                                              const float* __restrict__ bi,
                                              const float* __restrict__ bimg,
                                              float* __restrict__ out) {
    __shared__ float rbuf[4];
    __shared__ float sinv;
    int m = blockIdx.x, j = threadIdx.x;
    float* qrow = &g_q[m * IMGD];
    float acc[4] = {bi[j], 0.f, 0.f, 0.f};
    for (int k = 0; k < IMGD; k += 16) {
#pragma unroll
        for (int u = 0; u < 4; u++) {
            float4 qv = *(const float4*)&qrow[k + 4 * u];
            float4 bv = *(const float4*)&bimg[k + 4 * u];
            qv.x += bv.x; qv.y += bv.y; qv.z += bv.z; qv.w += bv.w;
            acc[u] = fmaf(qv.x, Wi[(k + 4 * u + 0) * DD + j], acc[u]);
            acc[u] = fmaf(qv.y, Wi[(k + 4 * u + 1) * DD + j], acc[u]);
            acc[u] = fmaf(qv.z, Wi[(k + 4 * u + 2) * DD + j], acc[u]);
            acc[u] = fmaf(qv.w, Wi[(k + 4 * u + 3) * DD + j], acc[u]);
        }
    }
    float a = (acc[0] + acc[1]) + (acc[2] + acc[3]);
    float s = a * a;
#pragma unroll
    for (int o = 16; o > 0; o >>= 1) s += __shfl_xor_sync(0xffffffffu, s, o);
    if ((j & 31) == 0) rbuf[j >> 5] = s;
    __syncthreads();
    if (j == 0) sinv = rsqrtf(rbuf[0] + rbuf[1] + rbuf[2] + rbuf[3]);
    __syncthreads();
    out[m * DD + j] = a * sinv;
    __syncthreads();                       // all reads of qrow done
    for (int k = j; k < IMGD; k += 128) qrow[k] = 0.0f;   // reset for next replay
}

// ---------------- graph head: l2norm(pooled @ W_g + b_g) -----------------------
__global__ void __launch_bounds__(128) k_ghead(const int* __restrict__ batch,
                                               const float* __restrict__ Wg,
                                               const float* __restrict__ bg,
                                               float* __restrict__ out) {
    int b = blockIdx.x, j = threadIdx.x;
    __shared__ float p[DD];
    __shared__ float rbuf[4];
    __shared__ float sinv;
    __shared__ int cnt_s;
    if (j == 0) {
        int lo = 0, hi = NN;                        // lower_bound(batch, b)
        while (lo < hi) { int mid = (lo + hi) >> 1; if (batch[mid] < b) lo = mid + 1; else hi = mid; }
        int lo2 = lo, hi2 = NN;                     // upper_bound(batch, b)
        while (lo2 < hi2) { int mid = (lo2 + hi2) >> 1; if (batch[mid] <= b) lo2 = mid + 1; else hi2 = mid; }
        cnt_s = lo2 - lo;
    }
    __syncthreads();
    float inv = 1.0f / fmaxf((float)cnt_s, 1.0f);
    p[j] = g_sums[b * DD + j] * inv;
    g_sums[b * DD + j] = 0.0f;                      // reset for next replay
    __syncthreads();
    float acc = bg[j];
#pragma unroll 8
    for (int k = 0; k < DD; k++) acc = fmaf(p[k], Wg[k * DD + j], acc);
    float s = acc * acc;
#pragma unroll
    for (int o = 16; o > 0; o >>= 1) s += __shfl_xor_sync(0xffffffffu, s, o);
    if ((j & 31) == 0) rbuf[j >> 5] = s;
    __syncthreads();
    if (j == 0) sinv = rsqrtf(rbuf[0] + rbuf[1] + rbuf[2] + rbuf[3]);
    __syncthreads();
    out[NBATCH * DD + b * DD + j] = acc * sinv;
}

// ---------------- launch --------------------------------------------------------
extern "C" void kernel_launch(void* const* d_in, const int* in_sizes, int n_in,
                              void* d_out, int out_size) {
    const float* images = (const float*)d_in[0];
    const int*   ids    = (const int*)d_in[1];
    const int*   src    = (const int*)d_in[2];
    const int*   dst    = (const int*)d_in[3];
    const float* ew     = (const float*)d_in[4];
    const int*   batch  = (const int*)d_in[5];
    const float* emb    = (const float*)d_in[6];
    const float* W_img  = (const float*)d_in[7];
    const float* b_img  = (const float*)d_in[8];
    const float* W_i    = (const float*)d_in[9];
    const float* b_i    = (const float*)d_in[10];
    const float* W1 = (const float*)d_in[11]; const float* b1 = (const float*)d_in[12];
    const float* W2 = (const float*)d_in[13]; const float* b2 = (const float*)d_in[14];
    const float* W3 = (const float*)d_in[15]; const float* b3 = (const float*)d_in[16];
    const float* W_g = (const float*)d_in[17]; const float* b_g = (const float*)d_in[18];
    float* out = (float*)d_out;

    (void)in_sizes; (void)n_in; (void)out_size;

    k_hist<<<NE / 256, 256>>>(dst);                      // 0
    k_scan1<<<SCAN_BLOCKS, 256>>>();                     // 1
    k_scan23<<<SCAN_BLOCKS, 256>>>();                    // 2
    k_img1<<<32 * IMG_KSPLIT, 256>>>(images, W_img);     // 3  <- usually profiled
    k_scatter<<<NE / 256, 256>>>(src, dst, ew);          // 4
    k_gather<<<NN / 8, 256>>>(ids, emb);                 // 5

    k_conv<0><<<CONV_BLOCKS, CTHREADS>>>(W1, b1, nullptr);  // 6  Y -> T
    k_conv<1><<<CONV_BLOCKS, CTHREADS>>>(W2, b2, nullptr);  // 7  T -> Y
    k_conv<2><<<CONV_BLOCKS, CTHREADS>>>(W3, b3, batch);    // 8  Y -> pool

    k_img2<<<NBATCH, 128>>>(W_i, b_i, b_img, out);       // 9
    k_ghead<<<NBATCH, 128>>>(batch, W_g, b_g, out);      // 10
}

// round 15
// speedup vs baseline: 1.0006x; 1.0006x over previous
#include <cuda_runtime.h>

// Problem constants (fixed by dataset)
#define NN     40000      // nodes
#define NE     640000     // edges
#define DD     128        // feature dim
#define NBATCH 32         // graphs
#define IMGD   4096       // image feature dim
#define SCAN_BLOCKS 157           // ceil(NN/256)
#define IMG_KSPLIT  32            // k_img1 k-splits (1024 blocks total)
#define PREP_THREADS 256
#define PREP_WARPS  (SCAN_BLOCKS * 8)     // 1256 warps in k_prep
#define CROWS   8                 // rows per conv block (warp per row)
#define CONV_BLOCKS (NN / CROWS)  // 5000

// ---------------- scratch (static device globals; zero at module load) --------
// Self-restoring invariant: g_hist, g_deg, g_bar, g_q, g_sums are zero before
// every replay; each consumer re-zeroes what it read.
__device__ int   g_hist[NN];
__device__ float g_deg[NN];
__device__ float g_dis[NN];
__device__ int   g_off[NN + 1];
__device__ int   g_cur[NN];
__device__ int   g_bsum[SCAN_BLOCKS];
__device__ int   g_bar;
__device__ int2  g_e[NE];         // (src, __float_as_int(w)) dst-sorted
__device__ float g_Y[NN * DD];    // feature ping buffer (dis-scaled)
__device__ float g_T[NN * DD];    // feature pong buffer
__device__ float g_q[NBATCH * IMGD];
__device__ float g_sums[NBATCH * DD];

__device__ __forceinline__ void red_add(float* p, float v) {
    asm volatile("red.global.add.f32 [%0], %1;" :: "l"(p), "f"(v) : "memory");
}

// ---------------- degree (float) + histogram (int) -----------------------------
__global__ void k_deg_hist(const int* __restrict__ dst, const float* __restrict__ ew) {
    int e = blockIdx.x * blockDim.x + threadIdx.x;
    if (e < NE) {
        int d = dst[e];
        atomicAdd(&g_deg[d], ew[e]);
        atomicAdd(&g_hist[d], 1);
    }
}

// ---------------- scan part 1: per-block exclusive scan (+hist reset) ----------
__global__ void k_scan1() {
    __shared__ int s[256];
    int tid = threadIdx.x;
    int i = blockIdx.x * 256 + tid;
    int v = 0;
    if (i < NN) { v = g_hist[i]; g_hist[i] = 0; }   // read + reset (self-restoring)
    s[tid] = v; __syncthreads();
    for (int o = 1; o < 256; o <<= 1) {
        int t = (tid >= o) ? s[tid - o] : 0;
        __syncthreads();
        s[tid] += t;
        __syncthreads();
    }
    if (i < NN) g_off[i] = s[tid] - v;
    if (tid == 255) g_bsum[blockIdx.x] = s[255];
}

// ---------------- prep: scan finalize + gather + [grid barrier] + scatter ------
// 157 blocks x 256 threads; all co-resident (tiny footprint), so the arrive+spin
// grid barrier is safe. g_bar is reset by k_conv<0> (runs strictly after).
__global__ void __launch_bounds__(PREP_THREADS) k_prep(const int* __restrict__ ids,
                                                       const float* __restrict__ emb,
                                                       const int* __restrict__ src,
                                                       const int* __restrict__ dst,
                                                       const float* __restrict__ ew) {
    __shared__ int s[256];
    int tid = threadIdx.x;
    // --- scan finalize (was scan23): rescan block sums, add base ---
    int v = (tid < SCAN_BLOCKS) ? g_bsum[tid] : 0;
    s[tid] = v; __syncthreads();
    for (int o = 1; o < 256; o <<= 1) {
        int t = (tid >= o) ? s[tid - o] : 0;
        __syncthreads();
        s[tid] += t;
        __syncthreads();
    }
    int base = (blockIdx.x > 0) ? s[blockIdx.x - 1] : 0;
    int i = blockIdx.x * 256 + tid;
    if (i < NN) {
        int val = g_off[i] + base;
        g_off[i] = val;
        g_cur[i] = val;
    }
    if (i == 0) g_off[NN] = NE;

    // --- gather: warp per row, strided; dis from g_deg (then reset deg) ---
    int wid = tid >> 5, lane = tid & 31;
    int w = blockIdx.x * 8 + wid;           // global warp id, 0..1255
    for (int row = w; row < NN; row += PREP_WARPS) {
        float ds = rsqrtf(1.0f + g_deg[row]);   // self-loop weight 1
        if (lane == 0) { g_dis[row] = ds; g_deg[row] = 0.0f; }  // reset for replay
        int id = ids[row];
        float4 fv = ((const float4*)emb)[id * (DD / 4) + lane];
        fv.x *= ds; fv.y *= ds; fv.z *= ds; fv.w *= ds;
        ((float4*)g_Y)[row * (DD / 4) + lane] = fv;
    }

    // --- grid barrier: all g_cur writes must land before any scatter ---
    __threadfence();
    __syncthreads();
    if (tid == 0) {
        atomicAdd(&g_bar, 1);
        while (atomicAdd(&g_bar, 0) < SCAN_BLOCKS) { }
    }
    __syncthreads();
    __threadfence();

    // --- scatter edges into dst-sorted int2 records ---
    int nthreads = SCAN_BLOCKS * PREP_THREADS;
    for (int e = blockIdx.x * PREP_THREADS + tid; e < NE; e += nthreads) {
        int d = dst[e];
        int p = atomicAdd(&g_cur[d], 1);
        g_e[p] = make_int2(src[e], __float_as_int(ew[e]));
    }
}

// ---------------- fused GCN conv ------------------------------------------------
// 256 threads, 8 rows/block, WARP PER ROW aggregation (plain global edge loads),
// then fused 8x128 GEMM.
// MODE 0: src g_Y -> dst g_T, relu epilogue      (conv 1)   <- PROFILED (idx 3)
// MODE 1: src g_T -> dst g_Y, relu epilogue      (conv 2)
// MODE 2: src g_Y -> mean-pool into g_sums       (conv 3)
template <int MODE>
__global__ void __launch_bounds__(256) k_conv(const float* __restrict__ W,
                                              const float* __restrict__ bias,
                                              const int* __restrict__ batch) {
    __shared__ float As[CROWS * DD];   // 4 KB: aggregated (dis-scaled) rows
    int tid = threadIdx.x;
    int wid = tid >> 5, lane = tid & 31;
    int r0 = blockIdx.x * CROWS;
    if (MODE == 0 && blockIdx.x == 0 && tid == 0) g_bar = 0;  // reset prep barrier
    const float4* Y4 = (const float4*)((MODE == 1) ? g_T : g_Y);
    const int2* __restrict__ ep = g_e;

    // Phase 1: warp per row; 8-wide unroll, dual accumulators
    {
        int row = r0 + wid;
        float ds = g_dis[row];
        float4 acc0 = Y4[row * 32 + lane];     // self loop
        float4 acc1 = make_float4(0.f, 0.f, 0.f, 0.f);
        int j = g_off[row], je = g_off[row + 1];
        for (; j + 8 <= je; j += 8) {
            int2 c0 = ep[j + 0], c1 = ep[j + 1], c2 = ep[j + 2], c3 = ep[j + 3];
            int2 c4 = ep[j + 4], c5 = ep[j + 5], c6 = ep[j + 6], c7 = ep[j + 7];
            float4 v0 = Y4[c0.x * 32 + lane];
            float4 v1 = Y4[c1.x * 32 + lane];
            float4 v2 = Y4[c2.x * 32 + lane];
            float4 v3 = Y4[c3.x * 32 + lane];
            float4 v4 = Y4[c4.x * 32 + lane];
            float4 v5 = Y4[c5.x * 32 + lane];
            float4 v6 = Y4[c6.x * 32 + lane];
            float4 v7 = Y4[c7.x * 32 + lane];
            float w0 = __int_as_float(c0.y), w1 = __int_as_float(c1.y);
            float w2 = __int_as_float(c2.y), w3 = __int_as_float(c3.y);
            float w4 = __int_as_float(c4.y), w5 = __int_as_float(c5.y);
            float w6 = __int_as_float(c6.y), w7 = __int_as_float(c7.y);
            acc0.x = fmaf(w0, v0.x, acc0.x); acc0.y = fmaf(w0, v0.y, acc0.y);
            acc0.z = fmaf(w0, v0.z, acc0.z); acc0.w = fmaf(w0, v0.w, acc0.w);
            acc1.x = fmaf(w1, v1.x, acc1.x); acc1.y = fmaf(w1, v1.y, acc1.y);
            acc1.z = fmaf(w1, v1.z, acc1.z); acc1.w = fmaf(w1, v1.w, acc1.w);
            acc0.x = fmaf(w2, v2.x, acc0.x); acc0.y = fmaf(w2, v2.y, acc0.y);
            acc0.z = fmaf(w2, v2.z, acc0.z); acc0.w = fmaf(w2, v2.w, acc0.w);
            acc1.x = fmaf(w3, v3.x, acc1.x); acc1.y = fmaf(w3, v3.y, acc1.y);
            acc1.z = fmaf(w3, v3.z, acc1.z); acc1.w = fmaf(w3, v3.w, acc1.w);
            acc0.x = fmaf(w4, v4.x, acc0.x); acc0.y = fmaf(w4, v4.y, acc0.y);
            acc0.z = fmaf(w4, v4.z, acc0.z); acc0.w = fmaf(w4, v4.w, acc0.w);
            acc1.x = fmaf(w5, v5.x, acc1.x); acc1.y = fmaf(w5, v5.y, acc1.y);
            acc1.z = fmaf(w5, v5.z, acc1.z); acc1.w = fmaf(w5, v5.w, acc1.w);
            acc0.x = fmaf(w6, v6.x, acc0.x); acc0.y = fmaf(w6, v6.y, acc0.y);
            acc0.z = fmaf(w6, v6.z, acc0.z); acc0.w = fmaf(w6, v6.w, acc0.w);
            acc1.x = fmaf(w7, v7.x, acc1.x); acc1.y = fmaf(w7, v7.y, acc1.y);
            acc1.z = fmaf(w7, v7.z, acc1.z); acc1.w = fmaf(w7, v7.w, acc1.w);
        }
        for (; j < je; j++) {
            int2 e = ep[j];
            float w = __int_as_float(e.y);
            float4 v = Y4[e.x * 32 + lane];
            acc0.x = fmaf(w, v.x, acc0.x); acc0.y = fmaf(w, v.y, acc0.y);
            acc0.z = fmaf(w, v.z, acc0.z); acc0.w = fmaf(w, v.w, acc0.w);
        }
        float4 r;
        r.x = (acc0.x + acc1.x) * ds; r.y = (acc0.y + acc1.y) * ds;
        r.z = (acc0.z + acc1.z) * ds; r.w = (acc0.w + acc1.w) * ds;
        ((float4*)As)[wid * 32 + lane] = r;     // conflict-free
    }
    __syncthreads();

    // Phase 2: 8x128 @ 128x128 GEMM; a via smem broadcast, W via L1
    int c = tid & 31, rg = tid >> 5;     // rg = output row (0..7)
    const float4* W4 = (const float4*)W;
    float acc[4] = {0.f, 0.f, 0.f, 0.f};
#pragma unroll 8
    for (int k = 0; k < DD; k++) {
        float a = As[rg * DD + k];               // broadcast
        float4 w = __ldg(&W4[k * 32 + c]);       // L1-resident after warm
        acc[0] = fmaf(a, w.x, acc[0]); acc[1] = fmaf(a, w.y, acc[1]);
        acc[2] = fmaf(a, w.z, acc[2]); acc[3] = fmaf(a, w.w, acc[3]);
    }
    float4 b4 = ((const float4*)bias)[c];
    if (MODE != 2) {
        float* Out = (MODE == 0) ? g_T : g_Y;
        int row = r0 + rg;
        float dso = g_dis[row];
        float4 o = make_float4(fmaxf(acc[0] + b4.x, 0.f) * dso,
                               fmaxf(acc[1] + b4.y, 0.f) * dso,
                               fmaxf(acc[2] + b4.z, 0.f) * dso,
                               fmaxf(acc[3] + b4.w, 0.f) * dso);
        ((float4*)Out)[row * 32 + c] = o;
    } else {
        float4 o = make_float4(acc[0] + b4.x, acc[1] + b4.y,
                               acc[2] + b4.z, acc[3] + b4.w);
        int b0 = batch[r0], bL = batch[r0 + CROWS - 1];
        if (b0 == bL) {
            // whole block in one graph: smem pre-reduce, 128 atomics/block
            __syncthreads();                   // done reading As; reuse as staging
            float4* sp = (float4*)As;
            sp[rg * 32 + c] = o;
            __syncthreads();
            if (tid < 32) {
                float4 a = sp[tid];
#pragma unroll
                for (int g = 1; g < CROWS; g++) {
                    float4 t = sp[g * 32 + tid];
                    a.x += t.x; a.y += t.y; a.z += t.z; a.w += t.w;
                }
                float* pp = &g_sums[b0 * DD + tid * 4];
                red_add(pp + 0, a.x); red_add(pp + 1, a.y);
                red_add(pp + 2, a.z); red_add(pp + 3, a.w);
            }
        } else {
            int bb = batch[r0 + rg];
            float* pp = &g_sums[bb * DD + c * 4];
            red_add(pp + 0, o.x); red_add(pp + 1, o.y);
            red_add(pp + 2, o.z); red_add(pp + 3, o.w);
        }
    }
}

// ---------------- image GEMM 1: g_q += images @ W_img (deep split-K) -----------
__global__ void __launch_bounds__(256) k_img1(const float* __restrict__ images,
                                              const float* __restrict__ Wimg) {
    __shared__ float4 simg[32 * 32];   // [row][k4] for this block's 128-k chunk
    int ct = blockIdx.x & 31;
    int ks = blockIdx.x >> 5;
    int tid = threadIdx.x;
    int kbase = ks * 128;
    const float4* img4 = (const float4*)images;
    for (int i = tid; i < 1024; i += 256) {
        int r = i >> 5, k4 = i & 31;
        simg[i] = img4[r * (IMGD / 4) + (kbase >> 2) + k4];
    }
    __syncthreads();
    int c = tid & 31;
    int rg = tid >> 5;               // 8 row groups x 4 rows = 32 rows
    const float4* W4 = (const float4*)Wimg + (size_t)kbase * (IMGD / 4) + ct * 32 + c;
    float acc[4][4] = {};
#pragma unroll 2
    for (int k4 = 0; k4 < 32; k4++) {
        const float4* Wp = W4 + (size_t)k4 * 4 * (IMGD / 4);
        float4 w0 = __ldg(Wp);
        float4 w1 = __ldg(Wp + (IMGD / 4));
        float4 w2 = __ldg(Wp + 2 * (IMGD / 4));
        float4 w3 = __ldg(Wp + 3 * (IMGD / 4));
        float4 a0 = simg[(rg * 4 + 0) * 32 + k4];
        float4 a1 = simg[(rg * 4 + 1) * 32 + k4];
        float4 a2 = simg[(rg * 4 + 2) * 32 + k4];
        float4 a3 = simg[(rg * 4 + 3) * 32 + k4];
#define IMG_FMA(rr, av) \
        acc[rr][0] = fmaf(av.x, w0.x, acc[rr][0]); acc[rr][1] = fmaf(av.x, w0.y, acc[rr][1]); \
        acc[rr][2] = fmaf(av.x, w0.z, acc[rr][2]); acc[rr][3] = fmaf(av.x, w0.w, acc[rr][3]); \
        acc[rr][0] = fmaf(av.y, w1.x, acc[rr][0]); acc[rr][1] = fmaf(av.y, w1.y, acc[rr][1]); \
        acc[rr][2] = fmaf(av.y, w1.z, acc[rr][2]); acc[rr][3] = fmaf(av.y, w1.w, acc[rr][3]); \
        acc[rr][0] = fmaf(av.z, w2.x, acc[rr][0]); acc[rr][1] = fmaf(av.z, w2.y, acc[rr][1]); \
        acc[rr][2] = fmaf(av.z, w2.z, acc[rr][2]); acc[rr][3] = fmaf(av.z, w2.w, acc[rr][3]); \
        acc[rr][0] = fmaf(av.w, w3.x, acc[rr][0]); acc[rr][1] = fmaf(av.w, w3.y, acc[rr][1]); \
        acc[rr][2] = fmaf(av.w, w3.z, acc[rr][2]); acc[rr][3] = fmaf(av.w, w3.w, acc[rr][3]);
        IMG_FMA(0, a0)
        IMG_FMA(1, a1)
        IMG_FMA(2, a2)
        IMG_FMA(3, a3)
#undef IMG_FMA
    }
    int c0 = ct * 128 + c * 4;
#pragma unroll
    for (int rr = 0; rr < 4; rr++) {
        float* p = &g_q[(rg * 4 + rr) * IMGD + c0];
        red_add(p + 0, acc[rr][0]); red_add(p + 1, acc[rr][1]);
        red_add(p + 2, acc[rr][2]); red_add(p + 3, acc[rr][3]);
    }
}

// ---------------- image head: out = l2norm((q + b_img) @ W_i + b_i) ------------
// Resets g_q row to zero afterwards (self-restoring for next replay).
__global__ void __launch_bounds__(128) k_img2(const float* __restrict__ Wi,
                                              const float* __restrict__ bi,
                                              const float* __restrict__ bimg,
                                              float* __restrict__ out) {
    __shared__ float rbuf[4];
    __shared__ float sinv;
    int m = blockIdx.x, j = threadIdx.x;
    float* qrow = &g_q[m * IMGD];
    float acc[4] = {bi[j], 0.f, 0.f, 0.f};
    for (int k = 0; k < IMGD; k += 16) {
#pragma unroll
        for (int u = 0; u < 4; u++) {
            float4 qv = *(const float4*)&qrow[k + 4 * u];
            float4 bv = *(const float4*)&bimg[k + 4 * u];
            qv.x += bv.x; qv.y += bv.y; qv.z += bv.z; qv.w += bv.w;
            acc[u] = fmaf(qv.x, Wi[(k + 4 * u + 0) * DD + j], acc[u]);
            acc[u] = fmaf(qv.y, Wi[(k + 4 * u + 1) * DD + j], acc[u]);
            acc[u] = fmaf(qv.z, Wi[(k + 4 * u + 2) * DD + j], acc[u]);
            acc[u] = fmaf(qv.w, Wi[(k + 4 * u + 3) * DD + j], acc[u]);
        }
    }
    float a = (acc[0] + acc[1]) + (acc[2] + acc[3]);
    float s = a * a;
#pragma unroll
    for (int o = 16; o > 0; o >>= 1) s += __shfl_xor_sync(0xffffffffu, s, o);
    if ((j & 31) == 0) rbuf[j >> 5] = s;
    __syncthreads();
    if (j == 0) sinv = rsqrtf(rbuf[0] + rbuf[1] + rbuf[2] + rbuf[3]);
    __syncthreads();
    out[m * DD + j] = a * sinv;
    __syncthreads();                       // all reads of qrow done
    for (int k = j; k < IMGD; k += 128) qrow[k] = 0.0f;   // reset for next replay
}

// ---------------- graph head: l2norm(pooled @ W_g + b_g) -----------------------
__global__ void __launch_bounds__(128) k_ghead(const int* __restrict__ batch,
                                               const float* __restrict__ Wg,
                                               const float* __restrict__ bg,
                                               float* __restrict__ out) {
    int b = blockIdx.x, j = threadIdx.x;
    __shared__ float p[DD];
    __shared__ float rbuf[4];
    __shared__ float sinv;
    __shared__ int cnt_s;
    if (j == 0) {
        int lo = 0, hi = NN;                        // lower_bound(batch, b)
        while (lo < hi) { int mid = (lo + hi) >> 1; if (batch[mid] < b) lo = mid + 1; else hi = mid; }
        int lo2 = lo, hi2 = NN;                     // upper_bound(batch, b)
        while (lo2 < hi2) { int mid = (lo2 + hi2) >> 1; if (batch[mid] <= b) lo2 = mid + 1; else hi2 = mid; }
        cnt_s = lo2 - lo;
    }
    __syncthreads();
    float inv = 1.0f / fmaxf((float)cnt_s, 1.0f);
    p[j] = g_sums[b * DD + j] * inv;
    g_sums[b * DD + j] = 0.0f;                      // reset for next replay
    __syncthreads();
    float acc = bg[j];
#pragma unroll 8
    for (int k = 0; k < DD; k++) acc = fmaf(p[k], Wg[k * DD + j], acc);
    float s = acc * acc;
#pragma unroll
    for (int o = 16; o > 0; o >>= 1) s += __shfl_xor_sync(0xffffffffu, s, o);
    if ((j & 31) == 0) rbuf[j >> 5] = s;
    __syncthreads();
    if (j == 0) sinv = rsqrtf(rbuf[0] + rbuf[1] + rbuf[2] + rbuf[3]);
    __syncthreads();
    out[NBATCH * DD + b * DD + j] = acc * sinv;
}

// ---------------- launch --------------------------------------------------------
extern "C" void kernel_launch(void* const* d_in, const int* in_sizes, int n_in,
                              void* d_out, int out_size) {
    const float* images = (const float*)d_in[0];
    const int*   ids    = (const int*)d_in[1];
    const int*   src    = (const int*)d_in[2];
    const int*   dst    = (const int*)d_in[3];
    const float* ew     = (const float*)d_in[4];
    const int*   batch  = (const int*)d_in[5];
    const float* emb    = (const float*)d_in[6];
    const float* W_img  = (const float*)d_in[7];
    const float* b_img  = (const float*)d_in[8];
    const float* W_i    = (const float*)d_in[9];
    const float* b_i    = (const float*)d_in[10];
    const float* W1 = (const float*)d_in[11]; const float* b1 = (const float*)d_in[12];
    const float* W2 = (const float*)d_in[13]; const float* b2 = (const float*)d_in[14];
    const float* W3 = (const float*)d_in[15]; const float* b3 = (const float*)d_in[16];
    const float* W_g = (const float*)d_in[17]; const float* b_g = (const float*)d_in[18];
    float* out = (float*)d_out;

    (void)in_sizes; (void)n_in; (void)out_size;

    k_deg_hist<<<NE / 256, 256>>>(dst, ew);                   // 0
    k_scan1<<<SCAN_BLOCKS, 256>>>();                          // 1
    k_prep<<<SCAN_BLOCKS, PREP_THREADS>>>(ids, emb, src, dst, ew);  // 2
    k_conv<0><<<CONV_BLOCKS, 256>>>(W1, b1, nullptr);         // 3  <- PROFILED
    k_conv<1><<<CONV_BLOCKS, 256>>>(W2, b2, nullptr);         // 4
    k_conv<2><<<CONV_BLOCKS, 256>>>(W3, b3, batch);           // 5
    k_img1<<<32 * IMG_KSPLIT, 256>>>(images, W_img);          // 6
    k_img2<<<NBATCH, 128>>>(W_i, b_i, b_img, out);            // 7
    k_ghead<<<NBATCH, 128>>>(batch, W_g, b_g, out);           // 8
}

// round 17
// speedup vs baseline: 1.1066x; 1.1059x over previous
#include <cuda_runtime.h>

// Problem constants (fixed by dataset)
#define NN     40000      // nodes
#define NE     640000     // edges
#define DD     128        // feature dim
#define NBATCH 32         // graphs
#define IMGD   4096       // image feature dim
#define SCAN_BLOCKS 157           // ceil(NN/256)
#define IMG_KSPLIT  32            // k_img1 k-splits (1024 blocks total)
#define PREP_THREADS 256
#define PREP_WARPS  (SCAN_BLOCKS * 8)     // 1256 warps in k_prep
#define CROWS   32                // rows per conv block (warp aggregates 4)
#define CONV_BLOCKS (NN / CROWS)  // 1250

// ---------------- scratch (static device globals; zero at module load) --------
// Self-restoring invariant: g_hist, g_deg, g_bar, g_q, g_sums are zero before
// every replay; each consumer re-zeroes what it read.
__device__ int   g_hist[NN];
__device__ float g_deg[NN];
__device__ float g_dis[NN];
__device__ int   g_off[NN + 1];
__device__ int   g_cur[NN];
__device__ int   g_bsum[SCAN_BLOCKS];
__device__ int   g_bar;
__device__ int2  g_e[NE];         // (src, __float_as_int(w)) dst-sorted
__device__ float g_Y[NN * DD];    // feature ping buffer (dis-scaled)
__device__ float g_T[NN * DD];    // feature pong buffer
__device__ float g_q[NBATCH * IMGD];
__device__ float g_sums[NBATCH * DD];

__device__ __forceinline__ void red_add(float* p, float v) {
    asm volatile("red.global.add.f32 [%0], %1;" :: "l"(p), "f"(v) : "memory");
}

// ---------------- degree (float) + histogram (int) -----------------------------
__global__ void k_deg_hist(const int* __restrict__ dst, const float* __restrict__ ew) {
    int e = blockIdx.x * blockDim.x + threadIdx.x;
    if (e < NE) {
        int d = dst[e];
        atomicAdd(&g_deg[d], ew[e]);
        atomicAdd(&g_hist[d], 1);
    }
}

// ---------------- scan part 1: per-block exclusive scan (+hist reset) ----------
__global__ void k_scan1() {
    __shared__ int s[256];
    int tid = threadIdx.x;
    int i = blockIdx.x * 256 + tid;
    int v = 0;
    if (i < NN) { v = g_hist[i]; g_hist[i] = 0; }   // read + reset (self-restoring)
    s[tid] = v; __syncthreads();
    for (int o = 1; o < 256; o <<= 1) {
        int t = (tid >= o) ? s[tid - o] : 0;
        __syncthreads();
        s[tid] += t;
        __syncthreads();
    }
    if (i < NN) g_off[i] = s[tid] - v;
    if (tid == 255) g_bsum[blockIdx.x] = s[255];
}

// ---------------- prep: scan finalize + gather + [grid barrier] + scatter ------
// 157 blocks x 256 threads; all co-resident (tiny footprint), so the arrive+spin
// grid barrier is safe. g_bar is reset by k_conv<0> (runs strictly after).
__global__ void __launch_bounds__(PREP_THREADS) k_prep(const int* __restrict__ ids,
                                                       const float* __restrict__ emb,
                                                       const int* __restrict__ src,
                                                       const int* __restrict__ dst,
                                                       const float* __restrict__ ew) {
    __shared__ int s[256];
    int tid = threadIdx.x;
    // --- scan finalize: rescan block sums, add base ---
    int v = (tid < SCAN_BLOCKS) ? g_bsum[tid] : 0;
    s[tid] = v; __syncthreads();
    for (int o = 1; o < 256; o <<= 1) {
        int t = (tid >= o) ? s[tid - o] : 0;
        __syncthreads();
        s[tid] += t;
        __syncthreads();
    }
    int base = (blockIdx.x > 0) ? s[blockIdx.x - 1] : 0;
    int i = blockIdx.x * 256 + tid;
    if (i < NN) {
        int val = g_off[i] + base;
        g_off[i] = val;
        g_cur[i] = val;
    }
    if (i == 0) g_off[NN] = NE;

    // --- gather: warp per row, strided; dis from g_deg (then reset deg) ---
    int wid = tid >> 5, lane = tid & 31;
    int w = blockIdx.x * 8 + wid;           // global warp id, 0..1255
    for (int row = w; row < NN; row += PREP_WARPS) {
        float ds = rsqrtf(1.0f + g_deg[row]);   // self-loop weight 1
        if (lane == 0) { g_dis[row] = ds; g_deg[row] = 0.0f; }  // reset for replay
        int id = ids[row];
        float4 fv = ((const float4*)emb)[id * (DD / 4) + lane];
        fv.x *= ds; fv.y *= ds; fv.z *= ds; fv.w *= ds;
        ((float4*)g_Y)[row * (DD / 4) + lane] = fv;
    }

    // --- grid barrier: all g_cur writes must land before any scatter ---
    __threadfence();
    __syncthreads();
    if (tid == 0) {
        atomicAdd(&g_bar, 1);
        while (atomicAdd(&g_bar, 0) < SCAN_BLOCKS) { }
    }
    __syncthreads();
    __threadfence();

    // --- scatter edges into dst-sorted int2 records ---
    int nthreads = SCAN_BLOCKS * PREP_THREADS;
    for (int e = blockIdx.x * PREP_THREADS + tid; e < NE; e += nthreads) {
        int d = dst[e];
        int p = atomicAdd(&g_cur[d], 1);
        g_e[p] = make_int2(src[e], __float_as_int(ew[e]));
    }
}

// ---------------- fused GCN conv ------------------------------------------------
// 256 threads, 32 rows/block. Phase 1: warp aggregates 4 rows (8-wide unroll,
// dual accumulators). Phase 2: 32x128 GEMM, thread tile 4 rows x 4 cols with
// k-step-4 inner loop -> W wavefronts amortized over 4x more rows (L1 fix).
// MODE 0: src g_Y -> dst g_T, relu epilogue      (conv 1)   <- PROFILED (idx 3)
// MODE 1: src g_T -> dst g_Y, relu epilogue      (conv 2)
// MODE 2: src g_Y -> mean-pool into g_sums       (conv 3)
template <int MODE>
__global__ void __launch_bounds__(256, 4) k_conv(const float* __restrict__ W,
                                                 const float* __restrict__ bias,
                                                 const int* __restrict__ batch) {
    __shared__ float As[CROWS * DD];   // 16 KB: aggregated (dis-scaled) rows
    int tid = threadIdx.x;
    int wid = tid >> 5, lane = tid & 31;
    int r0 = blockIdx.x * CROWS;
    if (MODE == 0 && blockIdx.x == 0 && tid == 0) g_bar = 0;  // reset prep barrier
    const float4* Y4 = (const float4*)((MODE == 1) ? g_T : g_Y);
    const int2* __restrict__ ep = g_e;

    // Phase 1: warp aggregates rows r0+wid*4 .. +3
#pragma unroll 1
    for (int rr = 0; rr < 4; rr++) {
        int row = r0 + wid * 4 + rr;
        float ds = g_dis[row];
        float4 acc0 = Y4[row * 32 + lane];     // self loop
        float4 acc1 = make_float4(0.f, 0.f, 0.f, 0.f);
        int j = g_off[row], je = g_off[row + 1];
        for (; j + 8 <= je; j += 8) {
            int2 c0 = ep[j + 0], c1 = ep[j + 1], c2 = ep[j + 2], c3 = ep[j + 3];
            int2 c4 = ep[j + 4], c5 = ep[j + 5], c6 = ep[j + 6], c7 = ep[j + 7];
            float4 v0 = Y4[c0.x * 32 + lane];
            float4 v1 = Y4[c1.x * 32 + lane];
            float4 v2 = Y4[c2.x * 32 + lane];
            float4 v3 = Y4[c3.x * 32 + lane];
            float4 v4 = Y4[c4.x * 32 + lane];
            float4 v5 = Y4[c5.x * 32 + lane];
            float4 v6 = Y4[c6.x * 32 + lane];
            float4 v7 = Y4[c7.x * 32 + lane];
            float w0 = __int_as_float(c0.y), w1 = __int_as_float(c1.y);
            float w2 = __int_as_float(c2.y), w3 = __int_as_float(c3.y);
            float w4 = __int_as_float(c4.y), w5 = __int_as_float(c5.y);
            float w6 = __int_as_float(c6.y), w7 = __int_as_float(c7.y);
            acc0.x = fmaf(w0, v0.x, acc0.x); acc0.y = fmaf(w0, v0.y, acc0.y);
            acc0.z = fmaf(w0, v0.z, acc0.z); acc0.w = fmaf(w0, v0.w, acc0.w);
            acc1.x = fmaf(w1, v1.x, acc1.x); acc1.y = fmaf(w1, v1.y, acc1.y);
            acc1.z = fmaf(w1, v1.z, acc1.z); acc1.w = fmaf(w1, v1.w, acc1.w);
            acc0.x = fmaf(w2, v2.x, acc0.x); acc0.y = fmaf(w2, v2.y, acc0.y);
            acc0.z = fmaf(w2, v2.z, acc0.z); acc0.w = fmaf(w2, v2.w, acc0.w);
            acc1.x = fmaf(w3, v3.x, acc1.x); acc1.y = fmaf(w3, v3.y, acc1.y);
            acc1.z = fmaf(w3, v3.z, acc1.z); acc1.w = fmaf(w3, v3.w, acc1.w);
            acc0.x = fmaf(w4, v4.x, acc0.x); acc0.y = fmaf(w4, v4.y, acc0.y);
            acc0.z = fmaf(w4, v4.z, acc0.z); acc0.w = fmaf(w4, v4.w, acc0.w);
            acc1.x = fmaf(w5, v5.x, acc1.x); acc1.y = fmaf(w5, v5.y, acc1.y);
            acc1.z = fmaf(w5, v5.z, acc1.z); acc1.w = fmaf(w5, v5.w, acc1.w);
            acc0.x = fmaf(w6, v6.x, acc0.x); acc0.y = fmaf(w6, v6.y, acc0.y);
            acc0.z = fmaf(w6, v6.z, acc0.z); acc0.w = fmaf(w6, v6.w, acc0.w);
            acc1.x = fmaf(w7, v7.x, acc1.x); acc1.y = fmaf(w7, v7.y, acc1.y);
            acc1.z = fmaf(w7, v7.z, acc1.z); acc1.w = fmaf(w7, v7.w, acc1.w);
        }
        for (; j < je; j++) {
            int2 e = ep[j];
            float w = __int_as_float(e.y);
            float4 v = Y4[e.x * 32 + lane];
            acc0.x = fmaf(w, v.x, acc0.x); acc0.y = fmaf(w, v.y, acc0.y);
            acc0.z = fmaf(w, v.z, acc0.z); acc0.w = fmaf(w, v.w, acc0.w);
        }
        float4 r;
        r.x = (acc0.x + acc1.x) * ds; r.y = (acc0.y + acc1.y) * ds;
        r.z = (acc0.z + acc1.z) * ds; r.w = (acc0.w + acc1.w) * ds;
        ((float4*)As)[(wid * 4 + rr) * 32 + lane] = r;     // conflict-free
    }
    __syncthreads();

    // Phase 2: 32x128 @ 128x128 GEMM; thread = 4 rows x 4 cols, k-step 4.
    // a via LDS.128 broadcast (1 wf / 4k / row), W float4 coalesced via L1.
    int c = tid & 31, rg = tid >> 5;     // warp rg -> rows rg*4..rg*4+3
    const float4* W4 = (const float4*)W;
    const float* A0 = &As[(rg * 4 + 0) * DD];
    const float* A1 = &As[(rg * 4 + 1) * DD];
    const float* A2 = &As[(rg * 4 + 2) * DD];
    const float* A3 = &As[(rg * 4 + 3) * DD];
    float acc[4][4] = {};
#pragma unroll 2
    for (int k = 0; k < DD; k += 4) {
        float4 a0 = *(const float4*)(A0 + k);
        float4 a1 = *(const float4*)(A1 + k);
        float4 a2 = *(const float4*)(A2 + k);
        float4 a3 = *(const float4*)(A3 + k);
        float4 w0 = __ldg(&W4[(k + 0) * 32 + c]);
        float4 w1 = __ldg(&W4[(k + 1) * 32 + c]);
        float4 w2 = __ldg(&W4[(k + 2) * 32 + c]);
        float4 w3 = __ldg(&W4[(k + 3) * 32 + c]);
#define CONV_FMA(rr, av) \
        acc[rr][0] = fmaf(av.x, w0.x, acc[rr][0]); acc[rr][1] = fmaf(av.x, w0.y, acc[rr][1]); \
        acc[rr][2] = fmaf(av.x, w0.z, acc[rr][2]); acc[rr][3] = fmaf(av.x, w0.w, acc[rr][3]); \
        acc[rr][0] = fmaf(av.y, w1.x, acc[rr][0]); acc[rr][1] = fmaf(av.y, w1.y, acc[rr][1]); \
        acc[rr][2] = fmaf(av.y, w1.z, acc[rr][2]); acc[rr][3] = fmaf(av.y, w1.w, acc[rr][3]); \
        acc[rr][0] = fmaf(av.z, w2.x, acc[rr][0]); acc[rr][1] = fmaf(av.z, w2.y, acc[rr][1]); \
        acc[rr][2] = fmaf(av.z, w2.z, acc[rr][2]); acc[rr][3] = fmaf(av.z, w2.w, acc[rr][3]); \
        acc[rr][0] = fmaf(av.w, w3.x, acc[rr][0]); acc[rr][1] = fmaf(av.w, w3.y, acc[rr][1]); \
        acc[rr][2] = fmaf(av.w, w3.z, acc[rr][2]); acc[rr][3] = fmaf(av.w, w3.w, acc[rr][3]);
        CONV_FMA(0, a0)
        CONV_FMA(1, a1)
        CONV_FMA(2, a2)
        CONV_FMA(3, a3)
#undef CONV_FMA
    }
    float4 b4 = ((const float4*)bias)[c];
    if (MODE != 2) {
        float* Out = (MODE == 0) ? g_T : g_Y;
#pragma unroll
        for (int rr = 0; rr < 4; rr++) {
            int row = r0 + rg * 4 + rr;
            float dso = g_dis[row];
            float4 o = make_float4(fmaxf(acc[rr][0] + b4.x, 0.f) * dso,
                                   fmaxf(acc[rr][1] + b4.y, 0.f) * dso,
                                   fmaxf(acc[rr][2] + b4.z, 0.f) * dso,
                                   fmaxf(acc[rr][3] + b4.w, 0.f) * dso);
            ((float4*)Out)[row * 32 + c] = o;
        }
    } else {
        float4 o[4];
#pragma unroll
        for (int rr = 0; rr < 4; rr++)
            o[rr] = make_float4(acc[rr][0] + b4.x, acc[rr][1] + b4.y,
                                acc[rr][2] + b4.z, acc[rr][3] + b4.w);
        int b0 = batch[r0], bL = batch[r0 + CROWS - 1];
        if (b0 == bL) {
            // whole block in one graph: thread pre-sums its 4 rows, smem reduce
            float4 s4 = make_float4(o[0].x + o[1].x + o[2].x + o[3].x,
                                    o[0].y + o[1].y + o[2].y + o[3].y,
                                    o[0].z + o[1].z + o[2].z + o[3].z,
                                    o[0].w + o[1].w + o[2].w + o[3].w);
            __syncthreads();                   // done reading As; reuse as staging
            float4* sp = (float4*)As;
            sp[rg * 32 + c] = s4;
            __syncthreads();
            if (tid < 32) {
                float4 a = sp[tid];
#pragma unroll
                for (int g = 1; g < 8; g++) {
                    float4 t = sp[g * 32 + tid];
                    a.x += t.x; a.y += t.y; a.z += t.z; a.w += t.w;
                }
                float* pp = &g_sums[b0 * DD + tid * 4];
                red_add(pp + 0, a.x); red_add(pp + 1, a.y);
                red_add(pp + 2, a.z); red_add(pp + 3, a.w);
            }
        } else {
#pragma unroll
            for (int rr = 0; rr < 4; rr++) {
                int bb = batch[r0 + rg * 4 + rr];
                float* pp = &g_sums[bb * DD + c * 4];
                red_add(pp + 0, o[rr].x); red_add(pp + 1, o[rr].y);
                red_add(pp + 2, o[rr].z); red_add(pp + 3, o[rr].w);
            }
        }
    }
}

// ---------------- image GEMM 1: g_q += images @ W_img (deep split-K) -----------
__global__ void __launch_bounds__(256) k_img1(const float* __restrict__ images,
                                              const float* __restrict__ Wimg) {
    __shared__ float4 simg[32 * 32];   // [row][k4] for this block's 128-k chunk
    int ct = blockIdx.x & 31;
    int ks = blockIdx.x >> 5;
    int tid = threadIdx.x;
    int kbase = ks * 128;
    const float4* img4 = (const float4*)images;
    for (int i = tid; i < 1024; i += 256) {
        int r = i >> 5, k4 = i & 31;
        simg[i] = img4[r * (IMGD / 4) + (kbase >> 2) + k4];
    }
    __syncthreads();
    int c = tid & 31;
    int rg = tid >> 5;               // 8 row groups x 4 rows = 32 rows
    const float4* W4 = (const float4*)Wimg + (size_t)kbase * (IMGD / 4) + ct * 32 + c;
    float acc[4][4] = {};
#pragma unroll 2
    for (int k4 = 0; k4 < 32; k4++) {
        const float4* Wp = W4 + (size_t)k4 * 4 * (IMGD / 4);
        float4 w0 = __ldg(Wp);
        float4 w1 = __ldg(Wp + (IMGD / 4));
        float4 w2 = __ldg(Wp + 2 * (IMGD / 4));
        float4 w3 = __ldg(Wp + 3 * (IMGD / 4));
        float4 a0 = simg[(rg * 4 + 0) * 32 + k4];
        float4 a1 = simg[(rg * 4 + 1) * 32 + k4];
        float4 a2 = simg[(rg * 4 + 2) * 32 + k4];
        float4 a3 = simg[(rg * 4 + 3) * 32 + k4];
#define IMG_FMA(rr, av) \
        acc[rr][0] = fmaf(av.x, w0.x, acc[rr][0]); acc[rr][1] = fmaf(av.x, w0.y, acc[rr][1]); \
        acc[rr][2] = fmaf(av.x, w0.z, acc[rr][2]); acc[rr][3] = fmaf(av.x, w0.w, acc[rr][3]); \
        acc[rr][0] = fmaf(av.y, w1.x, acc[rr][0]); acc[rr][1] = fmaf(av.y, w1.y, acc[rr][1]); \
        acc[rr][2] = fmaf(av.y, w1.z, acc[rr][2]); acc[rr][3] = fmaf(av.y, w1.w, acc[rr][3]); \
        acc[rr][0] = fmaf(av.z, w2.x, acc[rr][0]); acc[rr][1] = fmaf(av.z, w2.y, acc[rr][1]); \
        acc[rr][2] = fmaf(av.z, w2.z, acc[rr][2]); acc[rr][3] = fmaf(av.z, w2.w, acc[rr][3]); \
        acc[rr][0] = fmaf(av.w, w3.x, acc[rr][0]); acc[rr][1] = fmaf(av.w, w3.y, acc[rr][1]); \
        acc[rr][2] = fmaf(av.w, w3.z, acc[rr][2]); acc[rr][3] = fmaf(av.w, w3.w, acc[rr][3]);
        IMG_FMA(0, a0)
        IMG_FMA(1, a1)
        IMG_FMA(2, a2)
        IMG_FMA(3, a3)
#undef IMG_FMA
    }
    int c0 = ct * 128 + c * 4;
#pragma unroll
    for (int rr = 0; rr < 4; rr++) {
        float* p = &g_q[(rg * 4 + rr) * IMGD + c0];
        red_add(p + 0, acc[rr][0]); red_add(p + 1, acc[rr][1]);
        red_add(p + 2, acc[rr][2]); red_add(p + 3, acc[rr][3]);
    }
}

// ---------------- image head: out = l2norm((q + b_img) @ W_i + b_i) ------------
// Resets g_q row to zero afterwards (self-restoring for next replay).
__global__ void __launch_bounds__(128) k_img2(const float* __restrict__ Wi,
                                              const float* __restrict__ bi,
                                              const float* __restrict__ bimg,
                                              float* __restrict__ out) {
    __shared__ float rbuf[4];
    __shared__ float sinv;
    int m = blockIdx.x, j = threadIdx.x;
    float* qrow = &g_q[m * IMGD];
    float acc[4] = {bi[j], 0.f, 0.f, 0.f};
    for (int k = 0; k < IMGD; k += 16) {
#pragma unroll
        for (int u = 0; u < 4; u++) {
            float4 qv = *(const float4*)&qrow[k + 4 * u];
            float4 bv = *(const float4*)&bimg[k + 4 * u];
            qv.x += bv.x; qv.y += bv.y; qv.z += bv.z; qv.w += bv.w;
            acc[u] = fmaf(qv.x, Wi[(k + 4 * u + 0) * DD + j], acc[u]);
            acc[u] = fmaf(qv.y, Wi[(k + 4 * u + 1) * DD + j], acc[u]);
            acc[u] = fmaf(qv.z, Wi[(k + 4 * u + 2) * DD + j], acc[u]);
            acc[u] = fmaf(qv.w, Wi[(k + 4 * u + 3) * DD + j], acc[u]);
        }
    }
    float a = (acc[0] + acc[1]) + (acc[2] + acc[3]);
    float s = a * a;
#pragma unroll
    for (int o = 16; o > 0; o >>= 1) s += __shfl_xor_sync(0xffffffffu, s, o);
    if ((j & 31) == 0) rbuf[j >> 5] = s;
    __syncthreads();
    if (j == 0) sinv = rsqrtf(rbuf[0] + rbuf[1] + rbuf[2] + rbuf[3]);
    __syncthreads();
    out[m * DD + j] = a * sinv;
    __syncthreads();                       // all reads of qrow done
    for (int k = j; k < IMGD; k += 128) qrow[k] = 0.0f;   // reset for next replay
}

// ---------------- graph head: l2norm(pooled @ W_g + b_g) -----------------------
__global__ void __launch_bounds__(128) k_ghead(const int* __restrict__ batch,
                                               const float* __restrict__ Wg,
                                               const float* __restrict__ bg,
                                               float* __restrict__ out) {
    int b = blockIdx.x, j = threadIdx.x;
    __shared__ float p[DD];
    __shared__ float rbuf[4];
    __shared__ float sinv;
    __shared__ int cnt_s;
    if (j == 0) {
        int lo = 0, hi = NN;                        // lower_bound(batch, b)
        while (lo < hi) { int mid = (lo + hi) >> 1; if (batch[mid] < b) lo = mid + 1; else hi = mid; }
        int lo2 = lo, hi2 = NN;                     // upper_bound(batch, b)
        while (lo2 < hi2) { int mid = (lo2 + hi2) >> 1; if (batch[mid] <= b) lo2 = mid + 1; else hi2 = mid; }
        cnt_s = lo2 - lo;
    }
    __syncthreads();
    float inv = 1.0f / fmaxf((float)cnt_s, 1.0f);
    p[j] = g_sums[b * DD + j] * inv;
    g_sums[b * DD + j] = 0.0f;                      // reset for next replay
    __syncthreads();
    float acc = bg[j];
#pragma unroll 8
    for (int k = 0; k < DD; k++) acc = fmaf(p[k], Wg[k * DD + j], acc);
    float s = acc * acc;
#pragma unroll
    for (int o = 16; o > 0; o >>= 1) s += __shfl_xor_sync(0xffffffffu, s, o);
    if ((j & 31) == 0) rbuf[j >> 5] = s;
    __syncthreads();
    if (j == 0) sinv = rsqrtf(rbuf[0] + rbuf[1] + rbuf[2] + rbuf[3]);
    __syncthreads();
    out[NBATCH * DD + b * DD + j] = acc * sinv;
}

// ---------------- launch --------------------------------------------------------
extern "C" void kernel_launch(void* const* d_in, const int* in_sizes, int n_in,
                              void* d_out, int out_size) {
    const float* images = (const float*)d_in[0];
    const int*   ids    = (const int*)d_in[1];
    const int*   src    = (const int*)d_in[2];
    const int*   dst    = (const int*)d_in[3];
    const float* ew     = (const float*)d_in[4];
    const int*   batch  = (const int*)d_in[5];
    const float* emb    = (const float*)d_in[6];
    const float* W_img  = (const float*)d_in[7];
    const float* b_img  = (const float*)d_in[8];
    const float* W_i    = (const float*)d_in[9];
    const float* b_i    = (const float*)d_in[10];
    const float* W1 = (const float*)d_in[11]; const float* b1 = (const float*)d_in[12];
    const float* W2 = (const float*)d_in[13]; const float* b2 = (const float*)d_in[14];
    const float* W3 = (const float*)d_in[15]; const float* b3 = (const float*)d_in[16];
    const float* W_g = (const float*)d_in[17]; const float* b_g = (const float*)d_in[18];
    float* out = (float*)d_out;

    (void)in_sizes; (void)n_in; (void)out_size;

    k_deg_hist<<<NE / 256, 256>>>(dst, ew);                   // 0
    k_scan1<<<SCAN_BLOCKS, 256>>>();                          // 1
    k_prep<<<SCAN_BLOCKS, PREP_THREADS>>>(ids, emb, src, dst, ew);  // 2
    k_conv<0><<<CONV_BLOCKS, 256>>>(W1, b1, nullptr);         // 3  <- PROFILED
    k_conv<1><<<CONV_BLOCKS, 256>>>(W2, b2, nullptr);         // 4
    k_conv<2><<<CONV_BLOCKS, 256>>>(W3, b3, batch);           // 5
    k_img1<<<32 * IMG_KSPLIT, 256>>>(images, W_img);          // 6
    k_img2<<<NBATCH, 128>>>(W_i, b_i, b_img, out);            // 7
    k_ghead<<<NBATCH, 128>>>(batch, W_g, b_g, out);           // 8
}